// round 9
// baseline (speedup 1.0000x reference)
#include <cuda_runtime.h>

#define NB        32
#define NPTS      16384
#define SGRID     768
#define GOUT      256
#define BLKS_PER_B 8
#define NBLOCKS   (NB * BLKS_PER_B)          // 256
#define THREADS   512
#define PTS_PER_BLK (NPTS / BLKS_PER_B)      // 2048
#define PTS_PER_THR (PTS_PER_BLK / THREADS)  // 4
#define OUT_HALF  ((size_t)NB * GOUT * GOUT * 3)   // 6,291,456 floats
#define BATCH_F   (GOUT * GOUT * 3)          // 196608 floats per batch per copy

// Persistent sync/scratch (device globals zero-init at load; counters are
// monotonic across replays — gen = ticket>>3 stays aligned, no reset needed).
__device__ unsigned g_counter[NB];
__device__ unsigned g_ready[NB];
__device__ int g_bmin0[NB * BLKS_PER_B];
__device__ int g_bmin1[NB * BLKS_PER_B];
__device__ int g_off0[NB];
__device__ int g_off1[NB];

__global__ void __launch_bounds__(THREADS, 2)
fused_kernel(const float* __restrict__ pc, const float* __restrict__ feat,
             float* __restrict__ out, int dual)
{
    const int bid = blockIdx.x;
    const int b   = bid / BLKS_PER_B;
    const int blk = bid % BLKS_PER_B;
    const int t   = threadIdx.x;

    // ---- zero this batch's output slice (both copies if dual) ----
    {
        const int n4 = BATCH_F / BLKS_PER_B / 4;      // 6144 float4 per block per copy
        float4 z = make_float4(0.f, 0.f, 0.f, 0.f);
        float4* o0 = (float4*)(out + (size_t)b * BATCH_F) + blk * n4;
        #pragma unroll 4
        for (int i = t; i < n4; i += THREADS) o0[i] = z;
        if (dual) {
            float4* o1 = (float4*)(out + OUT_HALF + (size_t)b * BATCH_F) + blk * n4;
            #pragma unroll 4
            for (int i = t; i < n4; i += THREADS) o1[i] = z;
        }
    }

    // ---- phase A: lattice coords for 4 points/thread, kept in registers ----
    const float S6 = (float)2.449489742783178;      // np.float32(np.sqrt(6.0))
    const float A  = __fdiv_rn(2.0f, S6);
    const float C  = __fdiv_rn(-1.0f, S6);

    const float* p = pc + (size_t)b * 3 * NPTS;
    int gl[PTS_PER_THR];
    int k0 = 0x7FFFFFFF, k1 = 0x7FFFFFFF;

    #pragma unroll
    for (int i = 0; i < PTS_PER_THR; i++) {
        const int n = blk * PTS_PER_BLK + i * THREADS + t;
        float p0 = p[n];
        float p1 = p[n + NPTS];
        float p2 = p[n + 2 * NPTS];

        // cuBLAS-style K-ascending FMA chain (bit-exact vs XLA dot)
        float e0 = __fmaf_rn(C, p2, __fmaf_rn(C, p1, __fmul_rn(A, p0)));
        float e1 = __fmaf_rn(C, p2, __fmaf_rn(A, p1, __fmul_rn(C, p0)));
        float e2 = __fmaf_rn(A, p2, __fmaf_rn(C, p1, __fmul_rn(C, p0)));

        float g0 = __fmul_rn(rintf(__fdiv_rn(e0, 3.0f)), 3.0f);
        float g1 = __fmul_rn(rintf(__fdiv_rn(e1, 3.0f)), 3.0f);
        float g2 = __fmul_rn(rintf(__fdiv_rn(e2, 3.0f)), 3.0f);
        float m0 = __fadd_rn(e0, -g0);
        float m1 = __fadd_rn(e1, -g1);
        float m2 = __fadd_rn(e2, -g2);

        // rank: stable descending sort semantics (ties -> lower index first)
        int r0 = (m1 > m0) + (m2 > m0);
        int r1 = (m0 >= m1) + (m2 > m1);

        int rs  = (int)__fdiv_rn(__fadd_rn(__fadd_rn(g0, g1), g2), 3.0f);
        int gi0 = (int)g0;
        int gi1 = (int)g1;

        int sg = 0, c0 = 0, c1 = 0;
        if (rs > 0)      { sg = -1; c0 = (r0 >= 3 - rs); c1 = (r1 >= 3 - rs); }
        else if (rs < 0) { sg =  1; c0 = (r0 < -rs);     c1 = (r1 < -rs);     }
        gi0 += 3 * sg * c0;
        gi1 += 3 * sg * c1;
        r0  += 3 * sg * c0 + rs;
        r1  += 3 * sg * c1 + rs;

        gl[i] = (gi0 & 0xFFFF) | (gi1 << 16);
        k0 = min(k0, gi0 - r0);   // min_j key comp = gl - rank  (rank in [0,2])
        k1 = min(k1, gi1 - r1);
    }

    // ---- block min reduction ----
    #pragma unroll
    for (int s = 16; s; s >>= 1) {
        k0 = min(k0, __shfl_xor_sync(0xFFFFFFFF, k0, s));
        k1 = min(k1, __shfl_xor_sync(0xFFFFFFFF, k1, s));
    }
    __shared__ int sr0[THREADS / 32], sr1[THREADS / 32];
    __shared__ int s_off0, s_off1;
    const int wid = t >> 5;
    if ((t & 31) == 0) { sr0[wid] = k0; sr1[wid] = k1; }
    __syncthreads();

    // ---- per-batch barrier via monotonic ticket counter ----
    if (t == 0) {
        int a0 = sr0[0], a1 = sr1[0];
        #pragma unroll
        for (int w = 1; w < THREADS / 32; w++) { a0 = min(a0, sr0[w]); a1 = min(a1, sr1[w]); }
        ((volatile int*)g_bmin0)[bid] = a0;
        ((volatile int*)g_bmin1)[bid] = a1;
        __threadfence();                              // publish blockmin + output zeros
        unsigned old = atomicAdd(&g_counter[b], 1u);
        unsigned gen = old >> 3;                      // 8 arrivals per batch per launch
        if ((old & (BLKS_PER_B - 1)) == BLKS_PER_B - 1) {
            __threadfence();                          // acquire others' blockmin
            int m0v = 0x7FFFFFFF, m1v = 0x7FFFFFFF;
            #pragma unroll
            for (int w = 0; w < BLKS_PER_B; w++) {
                int v0 = ((volatile int*)g_bmin0)[b * BLKS_PER_B + w];
                int v1 = ((volatile int*)g_bmin1)[b * BLKS_PER_B + w];
                m0v = min(m0v, v0); m1v = min(m1v, v1);
            }
            ((volatile int*)g_off0)[b] = m0v;
            ((volatile int*)g_off1)[b] = m1v;
            __threadfence();                          // release off
            atomicAdd(&g_ready[b], 1u);
        }
        while (atomicAdd(&g_ready[b], 0u) <= gen) { } // spin (all blocks co-resident)
        __threadfence();                              // acquire off + peer zeros
        s_off0 = ((volatile int*)g_off0)[b];
        s_off1 = ((volatile int*)g_off1)[b];
    }
    __syncthreads();

    // ---- phase B: scatter-add (bary == [1,0,0] exactly -> vertex 0 only) ----
    const int off0 = s_off0, off1 = s_off1;
    const int pick0 = ((-off0) % 3 + 3) % 3;
    const int pick1 = ((-off1) % 3 + 3) % 3;
    const float* f = feat + (size_t)b * 3 * NPTS;

    #pragma unroll
    for (int i = 0; i < PTS_PER_THR; i++) {
        const int n = blk * PTS_PER_BLK + i * THREADS + t;
        int v   = gl[i];
        int gl0 = (int)(short)(v & 0xFFFF);
        int gl1 = v >> 16;                   // arithmetic shift sign-extends
        int x0 = gl0 - off0;                 // >= 0 by construction
        int x1 = gl1 - off1;
        if (x0 < SGRID && x1 < SGRID) {      // JAX scatter drops OOB
            int r = (x0 - pick0) / 3;        // exact: x ≡ pick (mod 3)
            int c = (x1 - pick1) / 3;
            float f0 = f[n];
            float f1 = f[n + NPTS];
            float f2 = f[n + 2 * NPTS];
            size_t base = (((size_t)b * GOUT + r) * GOUT + c) * 3;
            atomicAdd(out + base + 0, f0);
            atomicAdd(out + base + 1, f1);
            atomicAdd(out + base + 2, f2);
            if (dual) {
                atomicAdd(out + OUT_HALF + base + 0, f0);
                atomicAdd(out + OUT_HALF + base + 1, f1);
                atomicAdd(out + OUT_HALF + base + 2, f2);
            }
        }
    }
}

extern "C" void kernel_launch(void* const* d_in, const int* in_sizes, int n_in,
                              void* d_out, int out_size) {
    const float* pc   = (const float*)d_in[0];
    const float* feat = (const float*)d_in[1];
    float* out = (float*)d_out;
    int dual = ((size_t)out_size >= 2 * OUT_HALF) ? 1 : 0;
    fused_kernel<<<NBLOCKS, THREADS>>>(pc, feat, out, dual);
}

// round 11
// speedup vs baseline: 1.4002x; 1.4002x over previous
#include <cuda_runtime.h>

#define NB        32
#define NPTS      16384
#define SGRID     768
#define GOUT      256
#define BLKS_PER_B 64
#define NBLOCKS   (NB * BLKS_PER_B)          // 2048
#define THREADS   256
#define OUT_HALF  ((size_t)NB * GOUT * GOUT * 3)   // 6,291,456 floats
#define TOT_F4_1  (OUT_HALF / 4)             // float4 count for one copy

// Scratch: per-point packed gl + per-block minima. Every slot is rewritten
// every launch (plain stores), so no init/reset is needed across replays.
__device__ int g_gl[NB * NPTS];
__device__ int g_bmin0[NBLOCKS];
__device__ int g_bmin1[NBLOCKS];

// Node 1: zero output (grid-stride) + lattice coords + per-block key minima.
__global__ void __launch_bounds__(THREADS)
phaseA_kernel(const float* __restrict__ pc, float* __restrict__ out, int dual)
{
    const int bid = blockIdx.x;
    const int b   = bid / BLKS_PER_B;
    const int blk = bid % BLKS_PER_B;
    const int t   = threadIdx.x;

    // ---- zero the output (both copies), grid-stride float4 ----
    {
        float4 z = make_float4(0.f, 0.f, 0.f, 0.f);
        float4* o = (float4*)out;
        const size_t tot = dual ? 2 * TOT_F4_1 : TOT_F4_1;
        for (size_t i = (size_t)bid * THREADS + t; i < tot; i += (size_t)NBLOCKS * THREADS)
            o[i] = z;
    }

    // ---- phase A: one point per thread ----
    const float S6 = (float)2.449489742783178;      // np.float32(np.sqrt(6.0))
    const float A  = __fdiv_rn(2.0f, S6);
    const float C  = __fdiv_rn(-1.0f, S6);

    const int n = blk * THREADS + t;                // point index in batch
    const float* p = pc + (size_t)b * 3 * NPTS;
    float p0 = p[n];
    float p1 = p[n + NPTS];
    float p2 = p[n + 2 * NPTS];

    // cuBLAS-style K-ascending FMA chain (bit-exact vs XLA dot)
    float e0 = __fmaf_rn(C, p2, __fmaf_rn(C, p1, __fmul_rn(A, p0)));
    float e1 = __fmaf_rn(C, p2, __fmaf_rn(A, p1, __fmul_rn(C, p0)));
    float e2 = __fmaf_rn(A, p2, __fmaf_rn(C, p1, __fmul_rn(C, p0)));

    float g0 = __fmul_rn(rintf(__fdiv_rn(e0, 3.0f)), 3.0f);
    float g1 = __fmul_rn(rintf(__fdiv_rn(e1, 3.0f)), 3.0f);
    float g2 = __fmul_rn(rintf(__fdiv_rn(e2, 3.0f)), 3.0f);
    float m0 = __fadd_rn(e0, -g0);
    float m1 = __fadd_rn(e1, -g1);
    float m2 = __fadd_rn(e2, -g2);

    // rank: stable descending sort semantics (ties -> lower index first)
    int r0 = (m1 > m0) + (m2 > m0);
    int r1 = (m0 >= m1) + (m2 > m1);

    int rs  = (int)__fdiv_rn(__fadd_rn(__fadd_rn(g0, g1), g2), 3.0f);
    int gi0 = (int)g0;
    int gi1 = (int)g1;

    int sg = 0, c0 = 0, c1 = 0;
    if (rs > 0)      { sg = -1; c0 = (r0 >= 3 - rs); c1 = (r1 >= 3 - rs); }
    else if (rs < 0) { sg =  1; c0 = (r0 < -rs);     c1 = (r1 < -rs);     }
    gi0 += 3 * sg * c0;
    gi1 += 3 * sg * c1;
    r0  += 3 * sg * c0 + rs;
    r1  += 3 * sg * c1 + rs;

    g_gl[b * NPTS + n] = (gi0 & 0xFFFF) | (gi1 << 16);

    // min_j key component = gl - rank (rank in [0,2] after correction)
    int k0 = gi0 - r0;
    int k1 = gi1 - r1;

    #pragma unroll
    for (int s = 16; s; s >>= 1) {
        k0 = min(k0, __shfl_xor_sync(0xFFFFFFFF, k0, s));
        k1 = min(k1, __shfl_xor_sync(0xFFFFFFFF, k1, s));
    }
    __shared__ int sr0[THREADS / 32], sr1[THREADS / 32];
    const int wid = t >> 5;
    if ((t & 31) == 0) { sr0[wid] = k0; sr1[wid] = k1; }
    __syncthreads();
    if (t == 0) {
        int a0 = sr0[0], a1 = sr1[0];
        #pragma unroll
        for (int w = 1; w < THREADS / 32; w++) { a0 = min(a0, sr0[w]); a1 = min(a1, sr1[w]); }
        g_bmin0[bid] = a0;            // plain store; kernel boundary publishes it
        g_bmin1[bid] = a1;
    }
}

// Node 2: reduce 64 block minima per batch (redundantly per block, cheap L2
// broadcast), then scatter-add features at vertex-0 cells (bary == [1,0,0]).
__global__ void __launch_bounds__(THREADS)
phaseB_kernel(const float* __restrict__ feat, float* __restrict__ out, int dual)
{
    const int bid = blockIdx.x;
    const int b   = bid / BLKS_PER_B;
    const int blk = bid % BLKS_PER_B;
    const int t   = threadIdx.x;

    __shared__ int s_off0, s_off1;
    if (t < 32) {                                    // warp 0 reduces 64 values
        int base = b * BLKS_PER_B;
        int a0 = min(g_bmin0[base + t], g_bmin0[base + 32 + t]);
        int a1 = min(g_bmin1[base + t], g_bmin1[base + 32 + t]);
        #pragma unroll
        for (int s = 16; s; s >>= 1) {
            a0 = min(a0, __shfl_xor_sync(0xFFFFFFFF, a0, s));
            a1 = min(a1, __shfl_xor_sync(0xFFFFFFFF, a1, s));
        }
        if (t == 0) { s_off0 = a0; s_off1 = a1; }
    }
    __syncthreads();

    const int off0 = s_off0, off1 = s_off1;
    const int pick0 = ((-off0) % 3 + 3) % 3;
    const int pick1 = ((-off1) % 3 + 3) % 3;

    const int n = blk * THREADS + t;
    int v   = g_gl[b * NPTS + n];
    int gl0 = (int)(short)(v & 0xFFFF);
    int gl1 = v >> 16;                   // arithmetic shift sign-extends
    int x0 = gl0 - off0;                 // >= 0 by construction
    int x1 = gl1 - off1;
    if (x0 < SGRID && x1 < SGRID) {      // JAX scatter drops OOB
        int r = (x0 - pick0) / 3;        // exact: x ≡ pick (mod 3)
        int c = (x1 - pick1) / 3;
        const float* f = feat + (size_t)b * 3 * NPTS;
        float f0 = f[n];
        float f1 = f[n + NPTS];
        float f2 = f[n + 2 * NPTS];
        size_t base = (((size_t)b * GOUT + r) * GOUT + c) * 3;
        atomicAdd(out + base + 0, f0);
        atomicAdd(out + base + 1, f1);
        atomicAdd(out + base + 2, f2);
        if (dual) {
            atomicAdd(out + OUT_HALF + base + 0, f0);
            atomicAdd(out + OUT_HALF + base + 1, f1);
            atomicAdd(out + OUT_HALF + base + 2, f2);
        }
    }
}

extern "C" void kernel_launch(void* const* d_in, const int* in_sizes, int n_in,
                              void* d_out, int out_size) {
    const float* pc   = (const float*)d_in[0];
    const float* feat = (const float*)d_in[1];
    float* out = (float*)d_out;
    int dual = ((size_t)out_size >= 2 * OUT_HALF) ? 1 : 0;
    phaseA_kernel<<<NBLOCKS, THREADS>>>(pc, out, dual);
    phaseB_kernel<<<NBLOCKS, THREADS>>>(feat, out, dual);
}

// round 12
// speedup vs baseline: 1.8374x; 1.3123x over previous
#include <cuda_runtime.h>

#define NB        32
#define NPTS      16384
#define SGRID     768
#define GOUT      256
#define BLKS_PER_B 64
#define NBLOCKS   (NB * BLKS_PER_B)          // 2048
#define THREADS   256
#define OUT_HALF  ((size_t)NB * GOUT * GOUT * 3)   // 6,291,456 floats
#define TOT_F4_1  (OUT_HALF / 4)             // float4 count for one copy

// Scratch: per-point packed gl + per-block minima. Every slot is rewritten
// every launch (plain stores), so no init/reset is needed across replays.
__device__ int g_gl[NB * NPTS];
__device__ int g_bmin0[NBLOCKS];
__device__ int g_bmin1[NBLOCKS];

__device__ __forceinline__ void red_add_f32(float* p, float v) {
    asm volatile("red.global.add.f32 [%0], %1;"
                 :: "l"(__cvta_generic_to_global(p)), "f"(v) : "memory");
}
__device__ __forceinline__ void red_add_v2f32(float* p, float a, float b) {
    asm volatile("red.global.add.v2.f32 [%0], {%1, %2};"
                 :: "l"(__cvta_generic_to_global(p)), "f"(a), "f"(b) : "memory");
}

// Node 1: zero copy0 (grid-stride) + lattice coords + per-block key minima.
__global__ void __launch_bounds__(THREADS)
phaseA_kernel(const float* __restrict__ pc, float* __restrict__ out)
{
    const int bid = blockIdx.x;
    const int b   = bid / BLKS_PER_B;
    const int blk = bid % BLKS_PER_B;
    const int t   = threadIdx.x;

    // ---- zero copy 0 only (phaseC fully overwrites copy 1) ----
    {
        float4 z = make_float4(0.f, 0.f, 0.f, 0.f);
        float4* o = (float4*)out;
        for (size_t i = (size_t)bid * THREADS + t; i < TOT_F4_1; i += (size_t)NBLOCKS * THREADS)
            o[i] = z;
    }

    // ---- phase A: one point per thread ----
    const float S6 = (float)2.449489742783178;      // np.float32(np.sqrt(6.0))
    const float A  = __fdiv_rn(2.0f, S6);
    const float C  = __fdiv_rn(-1.0f, S6);

    const int n = blk * THREADS + t;                // point index in batch
    const float* p = pc + (size_t)b * 3 * NPTS;
    float p0 = p[n];
    float p1 = p[n + NPTS];
    float p2 = p[n + 2 * NPTS];

    // cuBLAS-style K-ascending FMA chain (bit-exact vs XLA dot)
    float e0 = __fmaf_rn(C, p2, __fmaf_rn(C, p1, __fmul_rn(A, p0)));
    float e1 = __fmaf_rn(C, p2, __fmaf_rn(A, p1, __fmul_rn(C, p0)));
    float e2 = __fmaf_rn(A, p2, __fmaf_rn(C, p1, __fmul_rn(C, p0)));

    float g0 = __fmul_rn(rintf(__fdiv_rn(e0, 3.0f)), 3.0f);
    float g1 = __fmul_rn(rintf(__fdiv_rn(e1, 3.0f)), 3.0f);
    float g2 = __fmul_rn(rintf(__fdiv_rn(e2, 3.0f)), 3.0f);
    float m0 = __fadd_rn(e0, -g0);
    float m1 = __fadd_rn(e1, -g1);
    float m2 = __fadd_rn(e2, -g2);

    // rank: stable descending sort semantics (ties -> lower index first)
    int r0 = (m1 > m0) + (m2 > m0);
    int r1 = (m0 >= m1) + (m2 > m1);

    int rs  = (int)__fdiv_rn(__fadd_rn(__fadd_rn(g0, g1), g2), 3.0f);
    int gi0 = (int)g0;
    int gi1 = (int)g1;

    int sg = 0, c0 = 0, c1 = 0;
    if (rs > 0)      { sg = -1; c0 = (r0 >= 3 - rs); c1 = (r1 >= 3 - rs); }
    else if (rs < 0) { sg =  1; c0 = (r0 < -rs);     c1 = (r1 < -rs);     }
    gi0 += 3 * sg * c0;
    gi1 += 3 * sg * c1;
    r0  += 3 * sg * c0 + rs;
    r1  += 3 * sg * c1 + rs;

    g_gl[b * NPTS + n] = (gi0 & 0xFFFF) | (gi1 << 16);

    // min_j key component = gl - rank (rank in [0,2] after correction)
    int k0 = gi0 - r0;
    int k1 = gi1 - r1;

    #pragma unroll
    for (int s = 16; s; s >>= 1) {
        k0 = min(k0, __shfl_xor_sync(0xFFFFFFFF, k0, s));
        k1 = min(k1, __shfl_xor_sync(0xFFFFFFFF, k1, s));
    }
    __shared__ int sr0[THREADS / 32], sr1[THREADS / 32];
    const int wid = t >> 5;
    if ((t & 31) == 0) { sr0[wid] = k0; sr1[wid] = k1; }
    __syncthreads();
    if (t == 0) {
        int a0 = sr0[0], a1 = sr1[0];
        #pragma unroll
        for (int w = 1; w < THREADS / 32; w++) { a0 = min(a0, sr0[w]); a1 = min(a1, sr1[w]); }
        g_bmin0[bid] = a0;            // plain store; kernel boundary publishes it
        g_bmin1[bid] = a1;
    }
}

// Node 2: reduce block minima per batch, scatter-add into copy 0 only,
// 2 REDG per point (v2 + scalar, alignment-split on cell parity).
__global__ void __launch_bounds__(THREADS)
phaseB_kernel(const float* __restrict__ feat, float* __restrict__ out)
{
    const int bid = blockIdx.x;
    const int b   = bid / BLKS_PER_B;
    const int blk = bid % BLKS_PER_B;
    const int t   = threadIdx.x;

    __shared__ int s_off0, s_off1;
    if (t < 32) {                                    // warp 0 reduces 64 values
        int base = b * BLKS_PER_B;
        int a0 = min(g_bmin0[base + t], g_bmin0[base + 32 + t]);
        int a1 = min(g_bmin1[base + t], g_bmin1[base + 32 + t]);
        #pragma unroll
        for (int s = 16; s; s >>= 1) {
            a0 = min(a0, __shfl_xor_sync(0xFFFFFFFF, a0, s));
            a1 = min(a1, __shfl_xor_sync(0xFFFFFFFF, a1, s));
        }
        if (t == 0) { s_off0 = a0; s_off1 = a1; }
    }
    __syncthreads();

    const int off0 = s_off0, off1 = s_off1;
    const int pick0 = ((-off0) % 3 + 3) % 3;
    const int pick1 = ((-off1) % 3 + 3) % 3;

    const int n = blk * THREADS + t;
    int v   = g_gl[b * NPTS + n];
    int gl0 = (int)(short)(v & 0xFFFF);
    int gl1 = v >> 16;                   // arithmetic shift sign-extends
    int x0 = gl0 - off0;                 // >= 0 by construction
    int x1 = gl1 - off1;
    if (x0 < SGRID && x1 < SGRID) {      // JAX scatter drops OOB
        int r = (x0 - pick0) / 3;        // exact: x ≡ pick (mod 3)
        int c = (x1 - pick1) / 3;
        const float* f = feat + (size_t)b * 3 * NPTS;
        float f0 = f[n];
        float f1 = f[n + NPTS];
        float f2 = f[n + 2 * NPTS];
        size_t cell = ((size_t)b * GOUT + r) * GOUT + c;
        float* dst = out + cell * 3;
        if ((cell & 1) == 0) {           // base 8B-aligned
            red_add_v2f32(dst, f0, f1);
            red_add_f32(dst + 2, f2);
        } else {                          // base+1 8B-aligned
            red_add_f32(dst, f0);
            red_add_v2f32(dst + 1, f1, f2);
        }
    }
}

// Node 3: duplicate copy0 -> copy1 with plain vector stores.
__global__ void __launch_bounds__(THREADS)
phaseC_kernel(float* __restrict__ out)
{
    const float4* src = (const float4*)out;
    float4* dst = (float4*)(out + OUT_HALF);
    for (size_t i = (size_t)blockIdx.x * THREADS + threadIdx.x; i < TOT_F4_1;
         i += (size_t)NBLOCKS * THREADS)
        dst[i] = src[i];
}

extern "C" void kernel_launch(void* const* d_in, const int* in_sizes, int n_in,
                              void* d_out, int out_size) {
    const float* pc   = (const float*)d_in[0];
    const float* feat = (const float*)d_in[1];
    float* out = (float*)d_out;
    int dual = ((size_t)out_size >= 2 * OUT_HALF) ? 1 : 0;
    phaseA_kernel<<<NBLOCKS, THREADS>>>(pc, out);
    phaseB_kernel<<<NBLOCKS, THREADS>>>(feat, out);
    if (dual) phaseC_kernel<<<NBLOCKS, THREADS>>>(out);
}

// round 14
// speedup vs baseline: 2.0170x; 1.0977x over previous
#include <cuda_runtime.h>

#define NB        32
#define NPTS      16384
#define SGRID     768
#define GOUT      256
#define BLKS_PER_B 64
#define NBLOCKS   (NB * BLKS_PER_B)          // 2048
#define THREADS   256
#define GRIDTHREADS ((size_t)NBLOCKS * THREADS)    // 524288
#define OUT_HALF  ((size_t)NB * GOUT * GOUT * 3)   // 6,291,456 floats
#define TOT_F4_1  (OUT_HALF / 4)             // 1,572,864 = 3 * GRIDTHREADS exactly

// Scratch: per-point packed gl + per-block minima. Every slot is rewritten
// every launch (plain stores), so no init/reset is needed across replays.
__device__ int g_gl[NB * NPTS];
__device__ int g_bmin0[NBLOCKS];
__device__ int g_bmin1[NBLOCKS];

__device__ __forceinline__ void red_add_f32(float* p, float v) {
    asm volatile("red.global.add.f32 [%0], %1;"
                 :: "l"(__cvta_generic_to_global(p)), "f"(v) : "memory");
}
__device__ __forceinline__ void red_add_v2f32(float* p, float a, float b) {
    asm volatile("red.global.add.v2.f32 [%0], {%1, %2};"
                 :: "l"(__cvta_generic_to_global(p)), "f"(a), "f"(b) : "memory");
}

// Node 1: zero copy0 (exactly 3 float4/thread) + lattice coords + block minima.
__global__ void __launch_bounds__(THREADS)
phaseA_kernel(const float* __restrict__ pc, float* __restrict__ out)
{
    const int bid = blockIdx.x;
    const int b   = bid / BLKS_PER_B;
    const int blk = bid % BLKS_PER_B;
    const int t   = threadIdx.x;
    const size_t id = (size_t)bid * THREADS + t;

    // ---- zero copy 0 (phaseC fully overwrites copy 1): 3 stores, no loop ----
    {
        float4 z = make_float4(0.f, 0.f, 0.f, 0.f);
        float4* o = (float4*)out;
        o[id] = z;
        o[id + GRIDTHREADS] = z;
        o[id + 2 * GRIDTHREADS] = z;
    }

    // ---- phase A: one point per thread ----
    const float S6 = (float)2.449489742783178;      // np.float32(np.sqrt(6.0))
    const float A  = __fdiv_rn(2.0f, S6);
    const float C  = __fdiv_rn(-1.0f, S6);

    const int n = blk * THREADS + t;                // point index in batch
    const float* p = pc + (size_t)b * 3 * NPTS;
    float p0 = p[n];
    float p1 = p[n + NPTS];
    float p2 = p[n + 2 * NPTS];

    // cuBLAS-style K-ascending FMA chain (bit-exact vs XLA dot)
    float e0 = __fmaf_rn(C, p2, __fmaf_rn(C, p1, __fmul_rn(A, p0)));
    float e1 = __fmaf_rn(C, p2, __fmaf_rn(A, p1, __fmul_rn(C, p0)));
    float e2 = __fmaf_rn(A, p2, __fmaf_rn(C, p1, __fmul_rn(C, p0)));

    float g0 = __fmul_rn(rintf(__fdiv_rn(e0, 3.0f)), 3.0f);
    float g1 = __fmul_rn(rintf(__fdiv_rn(e1, 3.0f)), 3.0f);
    float g2 = __fmul_rn(rintf(__fdiv_rn(e2, 3.0f)), 3.0f);
    float m0 = __fadd_rn(e0, -g0);
    float m1 = __fadd_rn(e1, -g1);
    float m2 = __fadd_rn(e2, -g2);

    // rank: stable descending sort semantics (ties -> lower index first)
    int r0 = (m1 > m0) + (m2 > m0);
    int r1 = (m0 >= m1) + (m2 > m1);

    int gi0 = (int)g0;
    int gi1 = (int)g1;
    int gi2 = (int)g2;
    int rs  = (gi0 + gi1 + gi2) / 3;     // exact: sum of multiples of 3

    int sg = 0, c0 = 0, c1 = 0;
    if (rs > 0)      { sg = -1; c0 = (r0 >= 3 - rs); c1 = (r1 >= 3 - rs); }
    else if (rs < 0) { sg =  1; c0 = (r0 < -rs);     c1 = (r1 < -rs);     }
    gi0 += 3 * sg * c0;
    gi1 += 3 * sg * c1;
    r0  += 3 * sg * c0 + rs;
    r1  += 3 * sg * c1 + rs;

    g_gl[b * NPTS + n] = (gi0 & 0xFFFF) | (gi1 << 16);

    // min_j key component = gl - rank (rank in [0,2] after correction)
    int k0 = __reduce_min_sync(0xFFFFFFFF, gi0 - r0);   // REDUX.MIN
    int k1 = __reduce_min_sync(0xFFFFFFFF, gi1 - r1);

    __shared__ int sr0[THREADS / 32], sr1[THREADS / 32];
    const int wid = t >> 5;
    if ((t & 31) == 0) { sr0[wid] = k0; sr1[wid] = k1; }
    __syncthreads();
    if (t == 0) {
        int a0 = sr0[0], a1 = sr1[0];
        #pragma unroll
        for (int w = 1; w < THREADS / 32; w++) { a0 = min(a0, sr0[w]); a1 = min(a1, sr1[w]); }
        g_bmin0[bid] = a0;            // plain store; kernel boundary publishes it
        g_bmin1[bid] = a1;
    }
}

// Node 2 (PDL): reduce block minima per batch, scatter-add into copy 0,
// 2 REDG per point (v2 + scalar, alignment-split on cell parity).
__global__ void __launch_bounds__(THREADS)
phaseB_kernel(const float* __restrict__ feat, float* __restrict__ out)
{
#if __CUDA_ARCH__ >= 900
    cudaGridDependencySynchronize();   // PDL: wait for phaseA data
#endif
    const int bid = blockIdx.x;
    const int b   = bid / BLKS_PER_B;
    const int blk = bid % BLKS_PER_B;
    const int t   = threadIdx.x;

    __shared__ int s_off0, s_off1;
    if (t < 32) {                                    // warp 0 reduces 64 values
        int base = b * BLKS_PER_B;
        int a0 = min(g_bmin0[base + t], g_bmin0[base + 32 + t]);
        int a1 = min(g_bmin1[base + t], g_bmin1[base + 32 + t]);
        a0 = __reduce_min_sync(0xFFFFFFFF, a0);
        a1 = __reduce_min_sync(0xFFFFFFFF, a1);
        if (t == 0) { s_off0 = a0; s_off1 = a1; }
    }
    __syncthreads();

    const int off0 = s_off0, off1 = s_off1;
    const int pick0 = ((-off0) % 3 + 3) % 3;
    const int pick1 = ((-off1) % 3 + 3) % 3;

    const int n = blk * THREADS + t;
    int v   = g_gl[b * NPTS + n];
    int gl0 = (int)(short)(v & 0xFFFF);
    int gl1 = v >> 16;                   // arithmetic shift sign-extends
    int x0 = gl0 - off0;                 // >= 0 by construction
    int x1 = gl1 - off1;
    if (x0 < SGRID && x1 < SGRID) {      // JAX scatter drops OOB
        int r = (x0 - pick0) / 3;        // exact: x ≡ pick (mod 3)
        int c = (x1 - pick1) / 3;
        const float* f = feat + (size_t)b * 3 * NPTS;
        float f0 = f[n];
        float f1 = f[n + NPTS];
        float f2 = f[n + 2 * NPTS];
        size_t cell = ((size_t)b * GOUT + r) * GOUT + c;
        float* dst = out + cell * 3;
        if ((cell & 1) == 0) {           // base 8B-aligned
            red_add_v2f32(dst, f0, f1);
            red_add_f32(dst + 2, f2);
        } else {                          // base+1 8B-aligned
            red_add_f32(dst, f0);
            red_add_v2f32(dst + 1, f1, f2);
        }
    }
}

// Node 3 (PDL): duplicate copy0 -> copy1, 3 float4 per thread, no loop.
__global__ void __launch_bounds__(THREADS)
phaseC_kernel(float* __restrict__ out)
{
#if __CUDA_ARCH__ >= 900
    cudaGridDependencySynchronize();   // PDL: wait for all phaseB atomics
#endif
    const size_t id = (size_t)blockIdx.x * THREADS + threadIdx.x;
    const float4* src = (const float4*)out;
    float4* dst = (float4*)(out + OUT_HALF);
    dst[id] = src[id];
    dst[id + GRIDTHREADS] = src[id + GRIDTHREADS];
    dst[id + 2 * GRIDTHREADS] = src[id + 2 * GRIDTHREADS];
}

extern "C" void kernel_launch(void* const* d_in, const int* in_sizes, int n_in,
                              void* d_out, int out_size) {
    const float* pc   = (const float*)d_in[0];
    const float* feat = (const float*)d_in[1];
    float* out = (float*)d_out;
    int dual = ((size_t)out_size >= 2 * OUT_HALF) ? 1 : 0;

    phaseA_kernel<<<NBLOCKS, THREADS>>>(pc, out);

    cudaLaunchAttribute attr[1];
    attr[0].id = cudaLaunchAttributeProgrammaticStreamSerialization;
    attr[0].val.programmaticStreamSerializationAllowed = 1;

    cudaLaunchConfig_t cfg = {};
    cfg.gridDim = dim3(NBLOCKS);
    cfg.blockDim = dim3(THREADS);
    cfg.dynamicSmemBytes = 0;
    cfg.stream = 0;
    cfg.attrs = attr;
    cfg.numAttrs = 1;

    cudaLaunchKernelEx(&cfg, phaseB_kernel, feat, out);
    if (dual) cudaLaunchKernelEx(&cfg, phaseC_kernel, out);
}